// round 16
// baseline (speedup 1.0000x reference)
#include <cuda_runtime.h>
#include <cstdint>

// EMA scan: s_t = 0.9*s_{t-1} + 0.1*x_t
// x: (1024, 32, 1024) f32, state: (32, 1024) f32
// out: out (1024*32768 floats) then final_state (32768 floats)
//
// Exact single pass at the traffic floor (268.6 MB) and the mixed 1:1 R/W
// DRAM ceiling (~5.65 TB/s). R5 structure with TT=64/STAGES=3: halves the
// per-tile barrier + group-accounting overhead (16 tiles instead of 32)
// and lengthens uninterrupted store bursts. CTA = 128 threads = 128
// consecutive channels; stage = 64 t x 128 ch = 32 KB; 96 KB smem/CTA.

#define T_STEPS 1024
#define N_CH    32768
#define CH_CTA  128
#define TT      64                    // timesteps per stage
#define STAGES  3
#define NTILES  (T_STEPS / TT)        // 16
#define STAGE_FLOATS (TT * CH_CTA)    // 8192
#define STAGE_BYTES  (STAGE_FLOATS * 4) // 32768

__device__ __forceinline__ void cp_async16(uint32_t smem_addr, const void* gmem) {
    asm volatile("cp.async.cg.shared.global [%0], [%1], 16;"
                 :: "r"(smem_addr), "l"(gmem));
}
__device__ __forceinline__ void cp_commit() {
    asm volatile("cp.async.commit_group;");
}
__device__ __forceinline__ void cp_waitN() {
    asm volatile("cp.async.wait_group %0;" :: "n"(STAGES - 2));
}

__global__ __launch_bounds__(CH_CTA, 2)
void ema_scan_kernel(const float* __restrict__ x,
                     const float* __restrict__ state,
                     float* __restrict__ out)
{
    extern __shared__ float smem[];   // [STAGES][TT][CH_CTA]

    const int tid = threadIdx.x;                 // 0..127
    const int c0  = blockIdx.x * CH_CTA;
    const int c   = c0 + tid;

    // loader mapping: 128 threads x 16B = 2 KB = 4 rows/round, 16 rounds/stage
    const int f4col  = tid & 31;                 // float4 column within row
    const int rowgrp = tid >> 5;                 // 0..3

    uint32_t smem_base;
    asm("{ .reg .u64 t; cvta.to.shared.u64 t, %1; cvt.u32.u64 %0, t; }"
        : "=r"(smem_base) : "l"(smem));

    const char* gbase = (const char*)(x + (size_t)c0 + f4col * 4);

    auto issue_tile = [&](int k) {
        const uint32_t sbuf = smem_base + (uint32_t)(k % STAGES) * STAGE_BYTES
                            + rowgrp * (CH_CTA * 4) + f4col * 16;
        const char* g = gbase + ((size_t)k * TT + rowgrp) * (N_CH * 4);
        #pragma unroll
        for (int r = 0; r < TT / 4; r++) {       // rows rowgrp + 4r
            cp_async16(sbuf + (uint32_t)r * 4 * CH_CTA * 4,
                       g + (size_t)r * 4 * N_CH * 4);
        }
    };

    // prologue: stages 0..STAGES-2
    #pragma unroll
    for (int k = 0; k < STAGES - 1; k++) { issue_tile(k); cp_commit(); }

    float s = state[c];
    float* op = out + c;

    #pragma unroll 1
    for (int k = 0; k < NTILES; k++) {
        cp_waitN();            // tile k's group complete (<= STAGES-2 pending)
        __syncthreads();       // visibility + guards reuse of oldest buffer

        if (k + STAGES - 1 < NTILES) issue_tile(k + STAGES - 1);
        cp_commit();           // keep group accounting aligned

        const float* buf = smem + (k % STAGES) * STAGE_FLOATS;
        #pragma unroll
        for (int t = 0; t < TT; t++) {
            s = fmaf(s, 0.9f, buf[t * CH_CTA + tid] * 0.1f);
            __stcs(op + (size_t)(k * TT + t) * N_CH, s);
        }
    }

    out[(size_t)T_STEPS * N_CH + c] = s;   // final_state
}

extern "C" void kernel_launch(void* const* d_in, const int* in_sizes, int n_in,
                              void* d_out, int out_size)
{
    const float* x     = (const float*)d_in[0];
    const float* state = (const float*)d_in[1];
    float*       out   = (float*)d_out;

    static bool attr_set = false;
    if (!attr_set) {
        cudaFuncSetAttribute(ema_scan_kernel,
                             cudaFuncAttributeMaxDynamicSharedMemorySize,
                             STAGES * STAGE_BYTES);
        attr_set = true;
    }

    dim3 block(CH_CTA);
    dim3 grid(N_CH / CH_CTA);   // 256 CTAs
    ema_scan_kernel<<<grid, block, STAGES * STAGE_BYTES>>>(x, state, out);
}

// round 17
// speedup vs baseline: 1.0424x; 1.0424x over previous
#include <cuda_runtime.h>
#include <cstdint>

// EMA scan: s_t = 0.9*s_{t-1} + 0.1*x_t
// x: (1024, 32, 1024) f32, state: (32, 1024) f32
// out: out (1024*32768 floats) then final_state (32768 floats)
//
// FINAL. Exact single pass at the traffic floor (268.6 MB) running at the
// chip's mixed 1:1 read/write DRAM ceiling (~5.6-5.7 TB/s). Best-measured
// configuration (R13): CTA = 1 warp = 32 consecutive channels, 1024 CTAs
// (~6.92 CTAs/SM, wave imbalance 1.01), 4-stage cp.async SMEM read pipeline
// (tile = 32 t x 32 ch = 4 KB), __syncwarp-only sync, .wb default stores.
// Measured: kernel 37.6 us, DRAM 72.1%, rel_err 0.
// Exhaustively compared (R1-R16): warp count, float4 width, pipeline depth,
// tile height, bulk/TMA stores, L2 evict policies, .cs stores — all
// neutral-or-worse. The remaining DRAM idle is read/write turnaround at the
// memory controller, not recoverable from the SM side.

#define T_STEPS 1024
#define N_CH    32768
#define CH_CTA  32
#define TT      32                    // timesteps per stage
#define STAGES  4
#define NTILES  (T_STEPS / TT)        // 32
#define STAGE_BYTES (TT * CH_CTA * 4) // 4096

__device__ __forceinline__ void cp_async16(uint32_t smem_addr, const void* gmem) {
    asm volatile("cp.async.cg.shared.global [%0], [%1], 16;"
                 :: "r"(smem_addr), "l"(gmem));
}
__device__ __forceinline__ void cp_commit() {
    asm volatile("cp.async.commit_group;");
}
__device__ __forceinline__ void cp_waitN() {
    asm volatile("cp.async.wait_group %0;" :: "n"(STAGES - 2));
}

__global__ __launch_bounds__(CH_CTA, 8)
void ema_scan_kernel(const float* __restrict__ x,
                     const float* __restrict__ state,
                     float* __restrict__ out)
{
    extern __shared__ float smem[];   // [STAGES][TT][CH_CTA]

    const int tid = threadIdx.x;                 // 0..31
    const int c0  = blockIdx.x * CH_CTA;
    const int c   = c0 + tid;

    // loader mapping: 32 threads x 16B = 512 B = 4 rows/round, 8 rounds/stage
    const int f4col  = tid & 7;                  // float4 column within row
    const int rowgrp = tid >> 3;                 // 0..3

    uint32_t smem_base;
    asm("{ .reg .u64 t; cvta.to.shared.u64 t, %1; cvt.u32.u64 %0, t; }"
        : "=r"(smem_base) : "l"(smem));

    const char* gbase = (const char*)(x + (size_t)c0 + f4col * 4);

    auto issue_tile = [&](int k) {
        const uint32_t sbuf = smem_base + (uint32_t)(k & (STAGES - 1)) * STAGE_BYTES
                            + rowgrp * (CH_CTA * 4) + f4col * 16;
        const char* g = gbase + ((size_t)k * TT + rowgrp) * (N_CH * 4);
        #pragma unroll
        for (int r = 0; r < TT / 4; r++)         // rows rowgrp + 4r
            cp_async16(sbuf + (uint32_t)r * 4 * CH_CTA * 4,
                       g + (size_t)r * 4 * N_CH * 4);
    };

    // prologue: stages 0..STAGES-2
    #pragma unroll
    for (int k = 0; k < STAGES - 1; k++) { issue_tile(k); cp_commit(); }

    float s = state[c];
    float* op = out + c;

    #pragma unroll 1
    for (int k = 0; k < NTILES; k++) {
        cp_waitN();            // tile k's group complete (<= STAGES-2 pending)
        __syncwarp();          // cross-lane visibility; orders last tile's
                               // LDS before the oldest buffer is overwritten

        if (k + STAGES - 1 < NTILES) issue_tile(k + STAGES - 1);
        cp_commit();           // keep group accounting aligned

        const float* buf = smem + (k & (STAGES - 1)) * (TT * CH_CTA);
        #pragma unroll
        for (int t = 0; t < TT; t++) {
            s = fmaf(s, 0.9f, buf[t * CH_CTA + tid] * 0.1f);
            op[(size_t)(k * TT + t) * N_CH] = s;   // .wb default store
        }
    }

    out[(size_t)T_STEPS * N_CH + c] = s;   // final_state
}

extern "C" void kernel_launch(void* const* d_in, const int* in_sizes, int n_in,
                              void* d_out, int out_size)
{
    const float* x     = (const float*)d_in[0];
    const float* state = (const float*)d_in[1];
    float*       out   = (float*)d_out;

    static bool attr_set = false;
    if (!attr_set) {
        cudaFuncSetAttribute(ema_scan_kernel,
                             cudaFuncAttributeMaxDynamicSharedMemorySize,
                             STAGES * STAGE_BYTES);
        attr_set = true;
    }

    dim3 block(CH_CTA);
    dim3 grid(N_CH / CH_CTA);   // 1024 CTAs
    ema_scan_kernel<<<grid, block, STAGES * STAGE_BYTES>>>(x, state, out);
}